// round 14
// baseline (speedup 1.0000x reference)
#include <cuda_runtime.h>
#include <cuda_fp16.h>
#include <math.h>
#include <stdint.h>

// Problem dims
#define NB   8
#define SEQ  1024
#define TOK  (NB * SEQ)       // 8192
#define D    1152
#define FFD  4608
#define NH   16
#define HD   72
#define QKVN 3456             // 3*D

// ---------------------------------------------------------------------------
// Scratch (device globals)
// ---------------------------------------------------------------------------
__device__ __half g_xln[(size_t)TOK * D];
__device__ __half g_qkv[(size_t)TOK * QKVN];
__device__ __half g_ao[(size_t)TOK * D];
__device__ float  g_h2[(size_t)TOK * D];
__device__ __half g_ff[(size_t)TOK * FFD];
__device__ __half g_wqkv[(size_t)D * QKVN];
__device__ float  g_bqkv[QKVN];
__device__ __half g_wo[(size_t)D * D];
__device__ __half g_wfc1[(size_t)D * FFD];
__device__ __half g_wfc2[(size_t)FFD * D];

// ---------------------------------------------------------------------------
// helpers
// ---------------------------------------------------------------------------
__device__ __forceinline__ uint32_t smem_u32(const void* p) {
    return (uint32_t)__cvta_generic_to_shared(p);
}
__device__ __forceinline__ void ldsm_x4(uint32_t* r, uint32_t addr) {
    asm volatile("ldmatrix.sync.aligned.m8n8.x4.shared.b16 {%0,%1,%2,%3}, [%4];"
                 : "=r"(r[0]), "=r"(r[1]), "=r"(r[2]), "=r"(r[3]) : "r"(addr));
}
__device__ __forceinline__ void ldsm_x4_t(uint32_t* r, uint32_t addr) {
    asm volatile("ldmatrix.sync.aligned.m8n8.x4.trans.shared.b16 {%0,%1,%2,%3}, [%4];"
                 : "=r"(r[0]), "=r"(r[1]), "=r"(r[2]), "=r"(r[3]) : "r"(addr));
}
__device__ __forceinline__ void mma_f16(float* c, const uint32_t* a,
                                        uint32_t b0, uint32_t b1) {
    asm volatile(
        "mma.sync.aligned.m16n8k16.row.col.f32.f16.f16.f32 "
        "{%0,%1,%2,%3}, {%4,%5,%6,%7}, {%8,%9}, {%0,%1,%2,%3};\n"
        : "+f"(c[0]), "+f"(c[1]), "+f"(c[2]), "+f"(c[3])
        : "r"(a[0]), "r"(a[1]), "r"(a[2]), "r"(a[3]), "r"(b0), "r"(b1));
}
__device__ __forceinline__ uint2 f4_to_h4(float4 v) {
    __half2 lo = __floats2half2_rn(v.x, v.y);
    __half2 hi = __floats2half2_rn(v.z, v.w);
    uint2 r;
    r.x = *(uint32_t*)&lo;
    r.y = *(uint32_t*)&hi;
    return r;
}
__device__ __forceinline__ uint32_t packh2(float x, float y) {
    __half2 h = __floats2half2_rn(x, y);
    return *(uint32_t*)&h;
}
__device__ __forceinline__ void cp16(uint32_t dst, const void* src) {
    asm volatile("cp.async.cg.shared.global [%0], [%1], 16;" :: "r"(dst), "l"(src));
}
__device__ __forceinline__ void cp_commit() {
    asm volatile("cp.async.commit_group;");
}

// ---------------------------------------------------------------------------
// Weight conversion / packing
// ---------------------------------------------------------------------------
__global__ void pack_qkv(const float* __restrict__ qw, const float* __restrict__ kw,
                         const float* __restrict__ vw, const float* __restrict__ qb,
                         const float* __restrict__ kb, const float* __restrict__ vb,
                         __half* __restrict__ w16, float* __restrict__ b) {
    int idx = blockIdx.x * blockDim.x + threadIdx.x;
    int e = idx * 4;
    if (e < D * D) {
        int k = e / D, n = e % D;
        size_t o = (size_t)k * QKVN + n;
        *(uint2*)&w16[o]        = f4_to_h4(*(const float4*)(qw + e));
        *(uint2*)&w16[o + 1152] = f4_to_h4(*(const float4*)(kw + e));
        *(uint2*)&w16[o + 2304] = f4_to_h4(*(const float4*)(vw + e));
    }
    if (idx < D) {
        b[idx]        = qb[idx];
        b[idx + 1152] = kb[idx];
        b[idx + 2304] = vb[idx];
    }
}
__global__ void conv_h(const float* __restrict__ src, __half* __restrict__ dst, int n4) {
    int i = blockIdx.x * blockDim.x + threadIdx.x;
    if (i < n4)
        *(uint2*)&dst[(size_t)i * 4] = f4_to_h4(*(const float4*)(src + (size_t)i * 4));
}

// ---------------------------------------------------------------------------
// LayerNorm: fp32 in, fp16 out
// ---------------------------------------------------------------------------
__global__ void ln_kernel(const float* __restrict__ X, const float* __restrict__ gamma,
                          const float* __restrict__ beta, __half* __restrict__ Y) {
    int row = blockIdx.x;
    int tid = threadIdx.x;
    float4 v = ((const float4*)(X + (size_t)row * D))[tid];
    float s  = v.x + v.y + v.z + v.w;
    float sq = v.x * v.x + v.y * v.y + v.z * v.z + v.w * v.w;
    #pragma unroll
    for (int o = 16; o > 0; o >>= 1) {
        s  += __shfl_down_sync(0xffffffffu, s,  o);
        sq += __shfl_down_sync(0xffffffffu, sq, o);
    }
    __shared__ float ss[9], ssq[9];
    int w = tid >> 5, l = tid & 31;
    if (l == 0) { ss[w] = s; ssq[w] = sq; }
    __syncthreads();
    float ts = 0.f, tsq = 0.f;
    #pragma unroll
    for (int i = 0; i < 9; i++) { ts += ss[i]; tsq += ssq[i]; }
    const float invD = 1.0f / (float)D;
    float mean = ts * invD;
    float var  = tsq * invD - mean * mean;
    float rinv = rsqrtf(var + 1e-5f);
    float4 g = ((const float4*)gamma)[tid];
    float4 b = ((const float4*)beta)[tid];
    float4 o;
    o.x = (v.x - mean) * rinv * g.x + b.x;
    o.y = (v.y - mean) * rinv * g.y + b.y;
    o.z = (v.z - mean) * rinv * g.z + b.z;
    o.w = (v.w - mean) * rinv * g.w + b.w;
    *(uint2*)(Y + (size_t)row * D + tid * 4) = f4_to_h4(o);
}

// ---------------------------------------------------------------------------
// fp16 GEMM, 4-stage cp.async pipeline.
// CTA tile 256x128x32, 8 warps as 4x2, warp tile 64x64.
// Smem: 4 * (256*40 + 32*136) halves = 116,736 B.
// ---------------------------------------------------------------------------
#define GSTG 4
#define AP_  40
#define BP_  136
#define A_ST (256 * AP_)
#define B_ST (32 * BP_)
#define GEMM_SMEM ((GSTG * (A_ST + B_ST)) * 2)

__global__ __launch_bounds__(256, 1)
void gemm_h(const __half* __restrict__ A, const __half* __restrict__ W,
            const float* __restrict__ bias, const float* __restrict__ res,
            void* __restrict__ Cv, int M, int N, int K, int lda,
            int gelu_act, int out_half)
{
    extern __shared__ __half dsm[];
    __half* Asm = dsm;
    __half* Bsm = dsm + GSTG * A_ST;

    int tid  = threadIdx.x;
    int lane = tid & 31;
    int warp = tid >> 5;
    int mwbase = (warp >> 1) * 64;     // 4 warps in M
    int nwbase = (warp & 1) * 64;      // 2 warps in N
    int brow = blockIdx.y * 256;
    int bcol = blockIdx.x * 128;
    int g4 = lane >> 2;
    int t4 = lane & 3;

    int a_row = tid;                   // 0..255
    int b_row = tid >> 3;              // 0..31
    int b_c   = (tid & 7) * 16;        // 0..112

    const __half* Ap = A + (size_t)(brow + a_row) * lda;
    const __half* Wp = W + (size_t)b_row * N + bcol + b_c;

    uint32_t as_base = smem_u32(Asm) + (a_row * AP_) * 2;
    uint32_t bs_base = smem_u32(Bsm) + (b_row * BP_ + b_c) * 2;

    float acc[4][8][4];
    #pragma unroll
    for (int mt = 0; mt < 4; mt++)
        #pragma unroll
        for (int nt = 0; nt < 8; nt++)
            #pragma unroll
            for (int r = 0; r < 4; r++) acc[mt][nt][r] = 0.f;

    int nk = K / 32;
    #pragma unroll
    for (int s = 0; s < GSTG - 1; s++) {
        const __half* ap = Ap + s * 32;
        const __half* wp = Wp + (size_t)s * 32 * N;
        uint32_t ad = as_base + s * A_ST * 2;
        uint32_t bd = bs_base + s * B_ST * 2;
        cp16(ad,      ap);
        cp16(ad + 16, ap + 8);
        cp16(ad + 32, ap + 16);
        cp16(ad + 48, ap + 24);
        cp16(bd,      wp);
        cp16(bd + 16, wp + 8);
        cp_commit();
    }

    for (int kt = 0; kt < nk; kt++) {
        int cur = kt & (GSTG - 1);
        asm volatile("cp.async.wait_group %0;" :: "n"(GSTG - 2));
        __syncthreads();
        if (kt + GSTG - 1 < nk) {
            int nst = (kt + GSTG - 1) & (GSTG - 1);
            const __half* ap = Ap + (kt + GSTG - 1) * 32;
            const __half* wp = Wp + (size_t)(kt + GSTG - 1) * 32 * N;
            uint32_t ad = as_base + nst * A_ST * 2;
            uint32_t bd = bs_base + nst * B_ST * 2;
            cp16(ad,      ap);
            cp16(ad + 16, ap + 8);
            cp16(ad + 32, ap + 16);
            cp16(ad + 48, ap + 24);
            cp16(bd,      wp);
            cp16(bd + 16, wp + 8);
        }
        cp_commit();
        const __half* Abuf = Asm + cur * A_ST;
        const __half* Bbuf = Bsm + cur * B_ST;
        #pragma unroll
        for (int kk = 0; kk < 32; kk += 16) {
            uint32_t bfr[8][2];
            #pragma unroll
            for (int np = 0; np < 4; np++) {
                int kr = kk + (lane & 7) + ((lane >> 3) & 1) * 8;
                int nc = nwbase + np * 16 + (lane >> 4) * 8;
                uint32_t r[4];
                ldsm_x4_t(r, smem_u32(Bbuf + kr * BP_ + nc));
                bfr[np * 2][0] = r[0]; bfr[np * 2][1] = r[1];
                bfr[np * 2 + 1][0] = r[2]; bfr[np * 2 + 1][1] = r[3];
            }
            #pragma unroll
            for (int mt = 0; mt < 4; mt++) {
                int ar = mwbase + mt * 16 + (lane & 15);
                int ac = kk + (lane >> 4) * 8;
                uint32_t a[4];
                ldsm_x4(a, smem_u32(Abuf + ar * AP_ + ac));
                #pragma unroll
                for (int nt = 0; nt < 8; nt++)
                    mma_f16(acc[mt][nt], a, bfr[nt][0], bfr[nt][1]);
            }
        }
    }

    __syncthreads();
    #pragma unroll
    for (int mt = 0; mt < 4; mt++) {
        #pragma unroll
        for (int nt = 0; nt < 8; nt++) {
            int col  = bcol + nwbase + nt * 8 + t4 * 2;
            float bx = bias[col], by = bias[col + 1];
            #pragma unroll
            for (int half = 0; half < 2; half++) {
                size_t row = (size_t)(brow + mwbase + mt * 16 + g4 + half * 8);
                float ox = acc[mt][nt][half * 2 + 0] + bx;
                float oy = acc[mt][nt][half * 2 + 1] + by;
                if (gelu_act) {
                    ox = 0.5f * ox * (1.0f + erff(ox * 0.70710678118f));
                    oy = 0.5f * oy * (1.0f + erff(oy * 0.70710678118f));
                }
                if (out_half) {
                    __half* Ch = (__half*)Cv;
                    *(__half2*)(Ch + row * N + col) = __floats2half2_rn(ox, oy);
                } else {
                    if (res) {
                        const float2 r = *(const float2*)(res + row * N + col);
                        ox += r.x; oy += r.y;
                    }
                    *(float2*)((float*)Cv + row * N + col) = make_float2(ox, oy);
                }
            }
        }
    }
}

// ---------------------------------------------------------------------------
// Flash attention with cp.async double-buffered K/V blocks (R12, unchanged)
// ---------------------------------------------------------------------------
#define FAP 88
#define FTS (128 * FAP)

__global__ __launch_bounds__(256, 1)
void flash_attn(const __half* __restrict__ QKV, __half* __restrict__ O) {
    extern __shared__ __half fsm[];
    __half (*Qs)[FAP] = (__half (*)[FAP])fsm;
    __half* Kbuf[2] = { fsm + FTS,     fsm + 2 * FTS };
    __half* Vbuf[2] = { fsm + 3 * FTS, fsm + 4 * FTS };

    int bh = blockIdx.y;
    int b = bh >> 4, h = bh & 15;
    int row0 = blockIdx.x * 128;
    const __half* qbase = QKV + (size_t)b * SEQ * QKVN + h * HD;
    const __half* kbase = qbase + 1152;
    const __half* vbase = qbase + 2304;
    int tid = threadIdx.x;
    int lane = tid & 31;
    int warp = tid >> 5;
    int g4 = lane >> 2;
    int t4 = lane & 3;

    {
        const __half2 sc2 = __float2half2_rn(0.117851130198f);
        for (int i = tid; i < 128 * 18; i += 256) {
            int r = i / 18, c = (i % 18) * 4;
            uint2 u = *(const uint2*)(qbase + (size_t)(row0 + r) * QKVN + c);
            __half2 lo = __hmul2(*(__half2*)&u.x, sc2);
            __half2 hi = __hmul2(*(__half2*)&u.y, sc2);
            uint2 o;
            o.x = *(uint32_t*)&lo;
            o.y = *(uint32_t*)&hi;
            *(uint2*)&Qs[r][c] = o;
        }
        for (int i = tid; i < 128 * 2; i += 256) {
            int r = i >> 1, c = 72 + (i & 1) * 4;
            uint2 z = make_uint2(0u, 0u);
            *(uint2*)&Qs[r][c] = z;
            *(uint2*)&Kbuf[0][r * FAP + c] = z;
            *(uint2*)&Kbuf[1][r * FAP + c] = z;
        }
    }

    for (int i = tid; i < 128 * 9; i += 256) {
        int r = i / 9, c16 = i % 9;
        uint32_t doff = (r * FAP + c16 * 8) * 2;
        cp16(smem_u32(Kbuf[0]) + doff, kbase + (size_t)r * QKVN + c16 * 8);
        cp16(smem_u32(Vbuf[0]) + doff, vbase + (size_t)r * QKVN + c16 * 8);
    }
    cp_commit();
    asm volatile("cp.async.wait_group 0;");
    __syncthreads();

    uint32_t qf[5][4];
    #pragma unroll
    for (int kc = 0; kc < 5; kc++) {
        int ar = warp * 16 + (lane & 15);
        int ac = kc * 16 + (lane >> 4) * 8;
        ldsm_x4(qf[kc], smem_u32(&Qs[ar][ac]));
    }

    float m0 = -1e30f, m1 = -1e30f, l0 = 0.f, l1 = 0.f;
    float o[10][4];
    #pragma unroll
    for (int nt = 0; nt < 10; nt++)
        #pragma unroll
        for (int r = 0; r < 4; r++) o[nt][r] = 0.f;

    for (int jb = 0; jb < 8; jb++) {
        int buf = jb & 1;
        const __half* Ks = Kbuf[buf];
        const __half* Vs = Vbuf[buf];
        if (jb + 1 < 8) {
            int nb = buf ^ 1;
            int j0 = (jb + 1) * 128;
            for (int i = tid; i < 128 * 9; i += 256) {
                int r = i / 9, c16 = i % 9;
                uint32_t doff = (r * FAP + c16 * 8) * 2;
                cp16(smem_u32(Kbuf[nb]) + doff, kbase + (size_t)(j0 + r) * QKVN + c16 * 8);
                cp16(smem_u32(Vbuf[nb]) + doff, vbase + (size_t)(j0 + r) * QKVN + c16 * 8);
            }
            cp_commit();
        }

        float s[16][4];
        #pragma unroll
        for (int nt = 0; nt < 16; nt++)
            #pragma unroll
            for (int r = 0; r < 4; r++) s[nt][r] = 0.f;
        #pragma unroll
        for (int np = 0; np < 8; np++) {
            int nr = np * 16 + (lane & 7) + (lane >> 4) * 8;
            #pragma unroll
            for (int kc = 0; kc < 5; kc++) {
                int nc = kc * 16 + ((lane >> 3) & 1) * 8;
                uint32_t r[4];
                ldsm_x4(r, smem_u32(Ks + nr * FAP + nc));
                mma_f16(s[np * 2],     qf[kc], r[0], r[1]);
                mma_f16(s[np * 2 + 1], qf[kc], r[2], r[3]);
            }
        }

        float cm0 = -1e30f, cm1 = -1e30f;
        #pragma unroll
        for (int nt = 0; nt < 16; nt++) {
            cm0 = fmaxf(cm0, fmaxf(s[nt][0], s[nt][1]));
            cm1 = fmaxf(cm1, fmaxf(s[nt][2], s[nt][3]));
        }
        cm0 = fmaxf(cm0, __shfl_xor_sync(0xffffffffu, cm0, 1));
        cm0 = fmaxf(cm0, __shfl_xor_sync(0xffffffffu, cm0, 2));
        cm1 = fmaxf(cm1, __shfl_xor_sync(0xffffffffu, cm1, 1));
        cm1 = fmaxf(cm1, __shfl_xor_sync(0xffffffffu, cm1, 2));
        float nm0 = fmaxf(m0, cm0);
        float nm1 = fmaxf(m1, cm1);
        float f0 = __expf(m0 - nm0);
        float f1 = __expf(m1 - nm1);
        m0 = nm0; m1 = nm1;
        float sum0 = 0.f, sum1 = 0.f;
        #pragma unroll
        for (int nt = 0; nt < 16; nt++) {
            s[nt][0] = __expf(s[nt][0] - nm0);
            s[nt][1] = __expf(s[nt][1] - nm0);
            s[nt][2] = __expf(s[nt][2] - nm1);
            s[nt][3] = __expf(s[nt][3] - nm1);
            sum0 += s[nt][0] + s[nt][1];
            sum1 += s[nt][2] + s[nt][3];
        }
        l0 = l0 * f0 + sum0;
        l1 = l1 * f1 + sum1;
        #pragma unroll
        for (int nt = 0; nt < 10; nt++) {
            o[nt][0] *= f0; o[nt][1] *= f0;
            o[nt][2] *= f1; o[nt][3] *= f1;
        }

        #pragma unroll
        for (int kc2 = 0; kc2 < 8; kc2++) {
            uint32_t a[4];
            a[0] = packh2(s[kc2 * 2][0],     s[kc2 * 2][1]);
            a[1] = packh2(s[kc2 * 2][2],     s[kc2 * 2][3]);
            a[2] = packh2(s[kc2 * 2 + 1][0], s[kc2 * 2 + 1][1]);
            a[3] = packh2(s[kc2 * 2 + 1][2], s[kc2 * 2 + 1][3]);
            int kr = kc2 * 16 + (lane & 7) + ((lane >> 3) & 1) * 8;
            #pragma unroll
            for (int np = 0; np < 5; np++) {
                int nc = np * 16 + (lane >> 4) * 8;
                uint32_t r[4];
                ldsm_x4_t(r, smem_u32(Vs + kr * FAP + nc));
                mma_f16(o[np * 2],     a, r[0], r[1]);
                mma_f16(o[np * 2 + 1], a, r[2], r[3]);
            }
        }
        if (jb + 1 < 8) {
            asm volatile("cp.async.wait_group 0;");
            __syncthreads();
        }
    }

    l0 += __shfl_xor_sync(0xffffffffu, l0, 1);
    l0 += __shfl_xor_sync(0xffffffffu, l0, 2);
    l1 += __shfl_xor_sync(0xffffffffu, l1, 1);
    l1 += __shfl_xor_sync(0xffffffffu, l1, 2);
    float inv0 = 1.0f / l0;
    float inv1 = 1.0f / l1;
    #pragma unroll
    for (int nt = 0; nt < 9; nt++) {
        int col = h * HD + nt * 8 + t4 * 2;
        size_t r = (size_t)b * SEQ + row0 + warp * 16 + g4;
        *(__half2*)(O + r * D + col)       = __floats2half2_rn(o[nt][0] * inv0, o[nt][1] * inv0);
        *(__half2*)(O + (r + 8) * D + col) = __floats2half2_rn(o[nt][2] * inv1, o[nt][3] * inv1);
    }
}

// ---------------------------------------------------------------------------
// Launch
// ---------------------------------------------------------------------------
extern "C" void kernel_launch(void* const* d_in, const int* in_sizes, int n_in,
                              void* d_out, int out_size) {
    const float* hs    = (const float*)d_in[0];
    const float* ln1_w = (const float*)d_in[1];
    const float* ln1_b = (const float*)d_in[2];
    const float* q_w   = (const float*)d_in[3];
    const float* q_b   = (const float*)d_in[4];
    const float* k_w   = (const float*)d_in[5];
    const float* k_b   = (const float*)d_in[6];
    const float* v_w   = (const float*)d_in[7];
    const float* v_b   = (const float*)d_in[8];
    const float* o_w   = (const float*)d_in[9];
    const float* o_b   = (const float*)d_in[10];
    const float* ln2_w = (const float*)d_in[11];
    const float* ln2_b = (const float*)d_in[12];
    const float* fc1_w = (const float*)d_in[13];
    const float* fc1_b = (const float*)d_in[14];
    const float* fc2_w = (const float*)d_in[15];
    const float* fc2_b = (const float*)d_in[16];
    float* out = (float*)d_out;

    __half *xln, *qkv, *ao, *ff, *wqkv, *wo, *wfc1, *wfc2;
    float *h2, *bqkv;
    cudaGetSymbolAddress((void**)&xln,  g_xln);
    cudaGetSymbolAddress((void**)&qkv,  g_qkv);
    cudaGetSymbolAddress((void**)&ao,   g_ao);
    cudaGetSymbolAddress((void**)&h2,   g_h2);
    cudaGetSymbolAddress((void**)&ff,   g_ff);
    cudaGetSymbolAddress((void**)&wqkv, g_wqkv);
    cudaGetSymbolAddress((void**)&bqkv, g_bqkv);
    cudaGetSymbolAddress((void**)&wo,   g_wo);
    cudaGetSymbolAddress((void**)&wfc1, g_wfc1);
    cudaGetSymbolAddress((void**)&wfc2, g_wfc2);

    const int FA_SMEM = 5 * FTS * (int)sizeof(__half);          // 112,640 B
    cudaFuncSetAttribute(flash_attn, cudaFuncAttributeMaxDynamicSharedMemorySize,
                         FA_SMEM);
    cudaFuncSetAttribute(gemm_h, cudaFuncAttributeMaxDynamicSharedMemorySize,
                         GEMM_SMEM);                            // 116,736 B

    // 0. weight conversion / packing
    pack_qkv<<<(D * D / 4 + 255) / 256, 256>>>(q_w, k_w, v_w, q_b, k_b, v_b, wqkv, bqkv);
    conv_h<<<(D * D / 4 + 255) / 256, 256>>>(o_w, wo, D * D / 4);
    conv_h<<<(D * FFD / 4 + 255) / 256, 256>>>(fc1_w, wfc1, D * FFD / 4);
    conv_h<<<(FFD * D / 4 + 255) / 256, 256>>>(fc2_w, wfc2, FFD * D / 4);

    // 1. LN1 -> fp16
    ln_kernel<<<TOK, 288>>>(hs, ln1_w, ln1_b, xln);
    // 2. fused QKV projection
    gemm_h<<<dim3(QKVN / 128, TOK / 256), 256, GEMM_SMEM>>>(xln, wqkv, bqkv, nullptr, qkv,
                                                            TOK, QKVN, D, D, 0, 1);
    // 3-5. fused attention
    flash_attn<<<dim3(SEQ / 128, NB * NH), 256, FA_SMEM>>>(qkv, ao);
    // 6. O projection + residual1 (fp32 out)
    gemm_h<<<dim3(D / 128, TOK / 256), 256, GEMM_SMEM>>>(ao, wo, o_b, hs, h2,
                                                         TOK, D, D, D, 0, 0);
    // 7. LN2 -> fp16
    ln_kernel<<<TOK, 288>>>(h2, ln2_w, ln2_b, xln);
    // 8. FC1 + GELU (fp16 out)
    gemm_h<<<dim3(FFD / 128, TOK / 256), 256, GEMM_SMEM>>>(xln, wfc1, fc1_b, nullptr, ff,
                                                           TOK, FFD, D, D, 1, 1);
    // 9. FC2 + residual2 (fp32 out)
    gemm_h<<<dim3(D / 128, TOK / 256), 256, GEMM_SMEM>>>(ff, wfc2, fc2_b, h2, out,
                                                         TOK, D, FFD, FFD, 0, 0);
}

// round 15
// speedup vs baseline: 1.0012x; 1.0012x over previous
#include <cuda_runtime.h>
#include <cuda_fp16.h>
#include <math.h>
#include <stdint.h>

// Problem dims
#define NB   8
#define SEQ  1024
#define TOK  (NB * SEQ)       // 8192
#define D    1152
#define FFD  4608
#define NH   16
#define HD   72
#define QKVN 3456             // 3*D

// ---------------------------------------------------------------------------
// Scratch (device globals)
// ---------------------------------------------------------------------------
__device__ __half g_xln[(size_t)TOK * D];
__device__ __half g_qkv[(size_t)TOK * QKVN];
__device__ __half g_ao[(size_t)TOK * D];
__device__ float  g_h2[(size_t)TOK * D];
__device__ __half g_ff[(size_t)TOK * FFD];
__device__ __half g_wqkv[(size_t)D * QKVN];
__device__ float  g_bqkv[QKVN];
__device__ __half g_wo[(size_t)D * D];
__device__ __half g_wfc1[(size_t)D * FFD];
__device__ __half g_wfc2[(size_t)FFD * D];

// ---------------------------------------------------------------------------
// helpers
// ---------------------------------------------------------------------------
__device__ __forceinline__ uint32_t smem_u32(const void* p) {
    return (uint32_t)__cvta_generic_to_shared(p);
}
__device__ __forceinline__ void ldsm_x4(uint32_t* r, uint32_t addr) {
    asm volatile("ldmatrix.sync.aligned.m8n8.x4.shared.b16 {%0,%1,%2,%3}, [%4];"
                 : "=r"(r[0]), "=r"(r[1]), "=r"(r[2]), "=r"(r[3]) : "r"(addr));
}
__device__ __forceinline__ void ldsm_x4_t(uint32_t* r, uint32_t addr) {
    asm volatile("ldmatrix.sync.aligned.m8n8.x4.trans.shared.b16 {%0,%1,%2,%3}, [%4];"
                 : "=r"(r[0]), "=r"(r[1]), "=r"(r[2]), "=r"(r[3]) : "r"(addr));
}
__device__ __forceinline__ void mma_f16(float* c, const uint32_t* a,
                                        uint32_t b0, uint32_t b1) {
    asm volatile(
        "mma.sync.aligned.m16n8k16.row.col.f32.f16.f16.f32 "
        "{%0,%1,%2,%3}, {%4,%5,%6,%7}, {%8,%9}, {%0,%1,%2,%3};\n"
        : "+f"(c[0]), "+f"(c[1]), "+f"(c[2]), "+f"(c[3])
        : "r"(a[0]), "r"(a[1]), "r"(a[2]), "r"(a[3]), "r"(b0), "r"(b1));
}
__device__ __forceinline__ uint2 f4_to_h4(float4 v) {
    __half2 lo = __floats2half2_rn(v.x, v.y);
    __half2 hi = __floats2half2_rn(v.z, v.w);
    uint2 r;
    r.x = *(uint32_t*)&lo;
    r.y = *(uint32_t*)&hi;
    return r;
}
__device__ __forceinline__ uint32_t packh2(float x, float y) {
    __half2 h = __floats2half2_rn(x, y);
    return *(uint32_t*)&h;
}
__device__ __forceinline__ void cp16(uint32_t dst, const void* src) {
    asm volatile("cp.async.cg.shared.global [%0], [%1], 16;" :: "r"(dst), "l"(src));
}
__device__ __forceinline__ void cp_commit() {
    asm volatile("cp.async.commit_group;");
}

// ---------------------------------------------------------------------------
// Weight conversion / packing
// ---------------------------------------------------------------------------
__global__ void pack_qkv(const float* __restrict__ qw, const float* __restrict__ kw,
                         const float* __restrict__ vw, const float* __restrict__ qb,
                         const float* __restrict__ kb, const float* __restrict__ vb,
                         __half* __restrict__ w16, float* __restrict__ b) {
    int idx = blockIdx.x * blockDim.x + threadIdx.x;
    int e = idx * 4;
    if (e < D * D) {
        int k = e / D, n = e % D;
        size_t o = (size_t)k * QKVN + n;
        *(uint2*)&w16[o]        = f4_to_h4(*(const float4*)(qw + e));
        *(uint2*)&w16[o + 1152] = f4_to_h4(*(const float4*)(kw + e));
        *(uint2*)&w16[o + 2304] = f4_to_h4(*(const float4*)(vw + e));
    }
    if (idx < D) {
        b[idx]        = qb[idx];
        b[idx + 1152] = kb[idx];
        b[idx + 2304] = vb[idx];
    }
}
__global__ void conv_h(const float* __restrict__ src, __half* __restrict__ dst, int n4) {
    int i = blockIdx.x * blockDim.x + threadIdx.x;
    if (i < n4)
        *(uint2*)&dst[(size_t)i * 4] = f4_to_h4(*(const float4*)(src + (size_t)i * 4));
}

// ---------------------------------------------------------------------------
// LayerNorm: fp32 in, fp16 out
// ---------------------------------------------------------------------------
__global__ void ln_kernel(const float* __restrict__ X, const float* __restrict__ gamma,
                          const float* __restrict__ beta, __half* __restrict__ Y) {
    int row = blockIdx.x;
    int tid = threadIdx.x;
    float4 v = ((const float4*)(X + (size_t)row * D))[tid];
    float s  = v.x + v.y + v.z + v.w;
    float sq = v.x * v.x + v.y * v.y + v.z * v.z + v.w * v.w;
    #pragma unroll
    for (int o = 16; o > 0; o >>= 1) {
        s  += __shfl_down_sync(0xffffffffu, s,  o);
        sq += __shfl_down_sync(0xffffffffu, sq, o);
    }
    __shared__ float ss[9], ssq[9];
    int w = tid >> 5, l = tid & 31;
    if (l == 0) { ss[w] = s; ssq[w] = sq; }
    __syncthreads();
    float ts = 0.f, tsq = 0.f;
    #pragma unroll
    for (int i = 0; i < 9; i++) { ts += ss[i]; tsq += ssq[i]; }
    const float invD = 1.0f / (float)D;
    float mean = ts * invD;
    float var  = tsq * invD - mean * mean;
    float rinv = rsqrtf(var + 1e-5f);
    float4 g = ((const float4*)gamma)[tid];
    float4 b = ((const float4*)beta)[tid];
    float4 o;
    o.x = (v.x - mean) * rinv * g.x + b.x;
    o.y = (v.y - mean) * rinv * g.y + b.y;
    o.z = (v.z - mean) * rinv * g.z + b.z;
    o.w = (v.w - mean) * rinv * g.w + b.w;
    *(uint2*)(Y + (size_t)row * D + tid * 4) = f4_to_h4(o);
}

// ---------------------------------------------------------------------------
// fp16 GEMM, 4-stage cp.async pipeline.
// CTA tile 256x128x32, 8 warps as 4x2, warp tile 64x64.
// Smem: 4 * (256*40 + 32*136) halves = 116,736 B.
// ---------------------------------------------------------------------------
#define GSTG 4
#define AP_  40
#define BP_  136
#define A_ST (256 * AP_)
#define B_ST (32 * BP_)
#define GEMM_SMEM ((GSTG * (A_ST + B_ST)) * 2)

__global__ __launch_bounds__(256, 1)
void gemm_h(const __half* __restrict__ A, const __half* __restrict__ W,
            const float* __restrict__ bias, const float* __restrict__ res,
            void* __restrict__ Cv, int M, int N, int K, int lda,
            int gelu_act, int out_half)
{
    extern __shared__ __half dsm[];
    __half* Asm = dsm;
    __half* Bsm = dsm + GSTG * A_ST;

    int tid  = threadIdx.x;
    int lane = tid & 31;
    int warp = tid >> 5;
    int mwbase = (warp >> 1) * 64;     // 4 warps in M
    int nwbase = (warp & 1) * 64;      // 2 warps in N
    int brow = blockIdx.y * 256;
    int bcol = blockIdx.x * 128;
    int g4 = lane >> 2;
    int t4 = lane & 3;

    int a_row = tid;                   // 0..255
    int b_row = tid >> 3;              // 0..31
    int b_c   = (tid & 7) * 16;        // 0..112

    const __half* Ap = A + (size_t)(brow + a_row) * lda;
    const __half* Wp = W + (size_t)b_row * N + bcol + b_c;

    uint32_t as_base = smem_u32(Asm) + (a_row * AP_) * 2;
    uint32_t bs_base = smem_u32(Bsm) + (b_row * BP_ + b_c) * 2;

    float acc[4][8][4];
    #pragma unroll
    for (int mt = 0; mt < 4; mt++)
        #pragma unroll
        for (int nt = 0; nt < 8; nt++)
            #pragma unroll
            for (int r = 0; r < 4; r++) acc[mt][nt][r] = 0.f;

    int nk = K / 32;
    #pragma unroll
    for (int s = 0; s < GSTG - 1; s++) {
        const __half* ap = Ap + s * 32;
        const __half* wp = Wp + (size_t)s * 32 * N;
        uint32_t ad = as_base + s * A_ST * 2;
        uint32_t bd = bs_base + s * B_ST * 2;
        cp16(ad,      ap);
        cp16(ad + 16, ap + 8);
        cp16(ad + 32, ap + 16);
        cp16(ad + 48, ap + 24);
        cp16(bd,      wp);
        cp16(bd + 16, wp + 8);
        cp_commit();
    }

    for (int kt = 0; kt < nk; kt++) {
        int cur = kt & (GSTG - 1);
        asm volatile("cp.async.wait_group %0;" :: "n"(GSTG - 2));
        __syncthreads();
        if (kt + GSTG - 1 < nk) {
            int nst = (kt + GSTG - 1) & (GSTG - 1);
            const __half* ap = Ap + (kt + GSTG - 1) * 32;
            const __half* wp = Wp + (size_t)(kt + GSTG - 1) * 32 * N;
            uint32_t ad = as_base + nst * A_ST * 2;
            uint32_t bd = bs_base + nst * B_ST * 2;
            cp16(ad,      ap);
            cp16(ad + 16, ap + 8);
            cp16(ad + 32, ap + 16);
            cp16(ad + 48, ap + 24);
            cp16(bd,      wp);
            cp16(bd + 16, wp + 8);
        }
        cp_commit();
        const __half* Abuf = Asm + cur * A_ST;
        const __half* Bbuf = Bsm + cur * B_ST;
        #pragma unroll
        for (int kk = 0; kk < 32; kk += 16) {
            uint32_t bfr[8][2];
            #pragma unroll
            for (int np = 0; np < 4; np++) {
                int kr = kk + (lane & 7) + ((lane >> 3) & 1) * 8;
                int nc = nwbase + np * 16 + (lane >> 4) * 8;
                uint32_t r[4];
                ldsm_x4_t(r, smem_u32(Bbuf + kr * BP_ + nc));
                bfr[np * 2][0] = r[0]; bfr[np * 2][1] = r[1];
                bfr[np * 2 + 1][0] = r[2]; bfr[np * 2 + 1][1] = r[3];
            }
            #pragma unroll
            for (int mt = 0; mt < 4; mt++) {
                int ar = mwbase + mt * 16 + (lane & 15);
                int ac = kk + (lane >> 4) * 8;
                uint32_t a[4];
                ldsm_x4(a, smem_u32(Abuf + ar * AP_ + ac));
                #pragma unroll
                for (int nt = 0; nt < 8; nt++)
                    mma_f16(acc[mt][nt], a, bfr[nt][0], bfr[nt][1]);
            }
        }
    }

    __syncthreads();
    #pragma unroll
    for (int mt = 0; mt < 4; mt++) {
        #pragma unroll
        for (int nt = 0; nt < 8; nt++) {
            int col  = bcol + nwbase + nt * 8 + t4 * 2;
            float bx = bias[col], by = bias[col + 1];
            #pragma unroll
            for (int half = 0; half < 2; half++) {
                size_t row = (size_t)(brow + mwbase + mt * 16 + g4 + half * 8);
                float ox = acc[mt][nt][half * 2 + 0] + bx;
                float oy = acc[mt][nt][half * 2 + 1] + by;
                if (gelu_act) {
                    ox = 0.5f * ox * (1.0f + erff(ox * 0.70710678118f));
                    oy = 0.5f * oy * (1.0f + erff(oy * 0.70710678118f));
                }
                if (out_half) {
                    __half* Ch = (__half*)Cv;
                    *(__half2*)(Ch + row * N + col) = __floats2half2_rn(ox, oy);
                } else {
                    if (res) {
                        const float2 r = *(const float2*)(res + row * N + col);
                        ox += r.x; oy += r.y;
                    }
                    *(float2*)((float*)Cv + row * N + col) = make_float2(ox, oy);
                }
            }
        }
    }
}

// ---------------------------------------------------------------------------
// Flash attention with cp.async double-buffered K/V blocks (R12, unchanged)
// ---------------------------------------------------------------------------
#define FAP 88
#define FTS (128 * FAP)

__global__ __launch_bounds__(256, 1)
void flash_attn(const __half* __restrict__ QKV, __half* __restrict__ O) {
    extern __shared__ __half fsm[];
    __half (*Qs)[FAP] = (__half (*)[FAP])fsm;
    __half* Kbuf[2] = { fsm + FTS,     fsm + 2 * FTS };
    __half* Vbuf[2] = { fsm + 3 * FTS, fsm + 4 * FTS };

    int bh = blockIdx.y;
    int b = bh >> 4, h = bh & 15;
    int row0 = blockIdx.x * 128;
    const __half* qbase = QKV + (size_t)b * SEQ * QKVN + h * HD;
    const __half* kbase = qbase + 1152;
    const __half* vbase = qbase + 2304;
    int tid = threadIdx.x;
    int lane = tid & 31;
    int warp = tid >> 5;
    int g4 = lane >> 2;
    int t4 = lane & 3;

    {
        const __half2 sc2 = __float2half2_rn(0.117851130198f);
        for (int i = tid; i < 128 * 18; i += 256) {
            int r = i / 18, c = (i % 18) * 4;
            uint2 u = *(const uint2*)(qbase + (size_t)(row0 + r) * QKVN + c);
            __half2 lo = __hmul2(*(__half2*)&u.x, sc2);
            __half2 hi = __hmul2(*(__half2*)&u.y, sc2);
            uint2 o;
            o.x = *(uint32_t*)&lo;
            o.y = *(uint32_t*)&hi;
            *(uint2*)&Qs[r][c] = o;
        }
        for (int i = tid; i < 128 * 2; i += 256) {
            int r = i >> 1, c = 72 + (i & 1) * 4;
            uint2 z = make_uint2(0u, 0u);
            *(uint2*)&Qs[r][c] = z;
            *(uint2*)&Kbuf[0][r * FAP + c] = z;
            *(uint2*)&Kbuf[1][r * FAP + c] = z;
        }
    }

    for (int i = tid; i < 128 * 9; i += 256) {
        int r = i / 9, c16 = i % 9;
        uint32_t doff = (r * FAP + c16 * 8) * 2;
        cp16(smem_u32(Kbuf[0]) + doff, kbase + (size_t)r * QKVN + c16 * 8);
        cp16(smem_u32(Vbuf[0]) + doff, vbase + (size_t)r * QKVN + c16 * 8);
    }
    cp_commit();
    asm volatile("cp.async.wait_group 0;");
    __syncthreads();

    uint32_t qf[5][4];
    #pragma unroll
    for (int kc = 0; kc < 5; kc++) {
        int ar = warp * 16 + (lane & 15);
        int ac = kc * 16 + (lane >> 4) * 8;
        ldsm_x4(qf[kc], smem_u32(&Qs[ar][ac]));
    }

    float m0 = -1e30f, m1 = -1e30f, l0 = 0.f, l1 = 0.f;
    float o[10][4];
    #pragma unroll
    for (int nt = 0; nt < 10; nt++)
        #pragma unroll
        for (int r = 0; r < 4; r++) o[nt][r] = 0.f;

    for (int jb = 0; jb < 8; jb++) {
        int buf = jb & 1;
        const __half* Ks = Kbuf[buf];
        const __half* Vs = Vbuf[buf];
        if (jb + 1 < 8) {
            int nb = buf ^ 1;
            int j0 = (jb + 1) * 128;
            for (int i = tid; i < 128 * 9; i += 256) {
                int r = i / 9, c16 = i % 9;
                uint32_t doff = (r * FAP + c16 * 8) * 2;
                cp16(smem_u32(Kbuf[nb]) + doff, kbase + (size_t)(j0 + r) * QKVN + c16 * 8);
                cp16(smem_u32(Vbuf[nb]) + doff, vbase + (size_t)(j0 + r) * QKVN + c16 * 8);
            }
            cp_commit();
        }

        float s[16][4];
        #pragma unroll
        for (int nt = 0; nt < 16; nt++)
            #pragma unroll
            for (int r = 0; r < 4; r++) s[nt][r] = 0.f;
        #pragma unroll
        for (int np = 0; np < 8; np++) {
            int nr = np * 16 + (lane & 7) + (lane >> 4) * 8;
            #pragma unroll
            for (int kc = 0; kc < 5; kc++) {
                int nc = kc * 16 + ((lane >> 3) & 1) * 8;
                uint32_t r[4];
                ldsm_x4(r, smem_u32(Ks + nr * FAP + nc));
                mma_f16(s[np * 2],     qf[kc], r[0], r[1]);
                mma_f16(s[np * 2 + 1], qf[kc], r[2], r[3]);
            }
        }

        float cm0 = -1e30f, cm1 = -1e30f;
        #pragma unroll
        for (int nt = 0; nt < 16; nt++) {
            cm0 = fmaxf(cm0, fmaxf(s[nt][0], s[nt][1]));
            cm1 = fmaxf(cm1, fmaxf(s[nt][2], s[nt][3]));
        }
        cm0 = fmaxf(cm0, __shfl_xor_sync(0xffffffffu, cm0, 1));
        cm0 = fmaxf(cm0, __shfl_xor_sync(0xffffffffu, cm0, 2));
        cm1 = fmaxf(cm1, __shfl_xor_sync(0xffffffffu, cm1, 1));
        cm1 = fmaxf(cm1, __shfl_xor_sync(0xffffffffu, cm1, 2));
        float nm0 = fmaxf(m0, cm0);
        float nm1 = fmaxf(m1, cm1);
        float f0 = __expf(m0 - nm0);
        float f1 = __expf(m1 - nm1);
        m0 = nm0; m1 = nm1;
        float sum0 = 0.f, sum1 = 0.f;
        #pragma unroll
        for (int nt = 0; nt < 16; nt++) {
            s[nt][0] = __expf(s[nt][0] - nm0);
            s[nt][1] = __expf(s[nt][1] - nm0);
            s[nt][2] = __expf(s[nt][2] - nm1);
            s[nt][3] = __expf(s[nt][3] - nm1);
            sum0 += s[nt][0] + s[nt][1];
            sum1 += s[nt][2] + s[nt][3];
        }
        l0 = l0 * f0 + sum0;
        l1 = l1 * f1 + sum1;
        #pragma unroll
        for (int nt = 0; nt < 10; nt++) {
            o[nt][0] *= f0; o[nt][1] *= f0;
            o[nt][2] *= f1; o[nt][3] *= f1;
        }

        #pragma unroll
        for (int kc2 = 0; kc2 < 8; kc2++) {
            uint32_t a[4];
            a[0] = packh2(s[kc2 * 2][0],     s[kc2 * 2][1]);
            a[1] = packh2(s[kc2 * 2][2],     s[kc2 * 2][3]);
            a[2] = packh2(s[kc2 * 2 + 1][0], s[kc2 * 2 + 1][1]);
            a[3] = packh2(s[kc2 * 2 + 1][2], s[kc2 * 2 + 1][3]);
            int kr = kc2 * 16 + (lane & 7) + ((lane >> 3) & 1) * 8;
            #pragma unroll
            for (int np = 0; np < 5; np++) {
                int nc = np * 16 + (lane >> 4) * 8;
                uint32_t r[4];
                ldsm_x4_t(r, smem_u32(Vs + kr * FAP + nc));
                mma_f16(o[np * 2],     a, r[0], r[1]);
                mma_f16(o[np * 2 + 1], a, r[2], r[3]);
            }
        }
        if (jb + 1 < 8) {
            asm volatile("cp.async.wait_group 0;");
            __syncthreads();
        }
    }

    l0 += __shfl_xor_sync(0xffffffffu, l0, 1);
    l0 += __shfl_xor_sync(0xffffffffu, l0, 2);
    l1 += __shfl_xor_sync(0xffffffffu, l1, 1);
    l1 += __shfl_xor_sync(0xffffffffu, l1, 2);
    float inv0 = 1.0f / l0;
    float inv1 = 1.0f / l1;
    #pragma unroll
    for (int nt = 0; nt < 9; nt++) {
        int col = h * HD + nt * 8 + t4 * 2;
        size_t r = (size_t)b * SEQ + row0 + warp * 16 + g4;
        *(__half2*)(O + r * D + col)       = __floats2half2_rn(o[nt][0] * inv0, o[nt][1] * inv0);
        *(__half2*)(O + (r + 8) * D + col) = __floats2half2_rn(o[nt][2] * inv1, o[nt][3] * inv1);
    }
}

// ---------------------------------------------------------------------------
// Launch
// ---------------------------------------------------------------------------
extern "C" void kernel_launch(void* const* d_in, const int* in_sizes, int n_in,
                              void* d_out, int out_size) {
    const float* hs    = (const float*)d_in[0];
    const float* ln1_w = (const float*)d_in[1];
    const float* ln1_b = (const float*)d_in[2];
    const float* q_w   = (const float*)d_in[3];
    const float* q_b   = (const float*)d_in[4];
    const float* k_w   = (const float*)d_in[5];
    const float* k_b   = (const float*)d_in[6];
    const float* v_w   = (const float*)d_in[7];
    const float* v_b   = (const float*)d_in[8];
    const float* o_w   = (const float*)d_in[9];
    const float* o_b   = (const float*)d_in[10];
    const float* ln2_w = (const float*)d_in[11];
    const float* ln2_b = (const float*)d_in[12];
    const float* fc1_w = (const float*)d_in[13];
    const float* fc1_b = (const float*)d_in[14];
    const float* fc2_w = (const float*)d_in[15];
    const float* fc2_b = (const float*)d_in[16];
    float* out = (float*)d_out;

    __half *xln, *qkv, *ao, *ff, *wqkv, *wo, *wfc1, *wfc2;
    float *h2, *bqkv;
    cudaGetSymbolAddress((void**)&xln,  g_xln);
    cudaGetSymbolAddress((void**)&qkv,  g_qkv);
    cudaGetSymbolAddress((void**)&ao,   g_ao);
    cudaGetSymbolAddress((void**)&h2,   g_h2);
    cudaGetSymbolAddress((void**)&ff,   g_ff);
    cudaGetSymbolAddress((void**)&wqkv, g_wqkv);
    cudaGetSymbolAddress((void**)&bqkv, g_bqkv);
    cudaGetSymbolAddress((void**)&wo,   g_wo);
    cudaGetSymbolAddress((void**)&wfc1, g_wfc1);
    cudaGetSymbolAddress((void**)&wfc2, g_wfc2);

    const int FA_SMEM = 5 * FTS * (int)sizeof(__half);          // 112,640 B
    cudaFuncSetAttribute(flash_attn, cudaFuncAttributeMaxDynamicSharedMemorySize,
                         FA_SMEM);
    cudaFuncSetAttribute(gemm_h, cudaFuncAttributeMaxDynamicSharedMemorySize,
                         GEMM_SMEM);                            // 116,736 B

    // 0. weight conversion / packing
    pack_qkv<<<(D * D / 4 + 255) / 256, 256>>>(q_w, k_w, v_w, q_b, k_b, v_b, wqkv, bqkv);
    conv_h<<<(D * D / 4 + 255) / 256, 256>>>(o_w, wo, D * D / 4);
    conv_h<<<(D * FFD / 4 + 255) / 256, 256>>>(fc1_w, wfc1, D * FFD / 4);
    conv_h<<<(FFD * D / 4 + 255) / 256, 256>>>(fc2_w, wfc2, FFD * D / 4);

    // 1. LN1 -> fp16
    ln_kernel<<<TOK, 288>>>(hs, ln1_w, ln1_b, xln);
    // 2. fused QKV projection
    gemm_h<<<dim3(QKVN / 128, TOK / 256), 256, GEMM_SMEM>>>(xln, wqkv, bqkv, nullptr, qkv,
                                                            TOK, QKVN, D, D, 0, 1);
    // 3-5. fused attention
    flash_attn<<<dim3(SEQ / 128, NB * NH), 256, FA_SMEM>>>(qkv, ao);
    // 6. O projection + residual1 (fp32 out)
    gemm_h<<<dim3(D / 128, TOK / 256), 256, GEMM_SMEM>>>(ao, wo, o_b, hs, h2,
                                                         TOK, D, D, D, 0, 0);
    // 7. LN2 -> fp16
    ln_kernel<<<TOK, 288>>>(h2, ln2_w, ln2_b, xln);
    // 8. FC1 + GELU (fp16 out)
    gemm_h<<<dim3(FFD / 128, TOK / 256), 256, GEMM_SMEM>>>(xln, wfc1, fc1_b, nullptr, ff,
                                                           TOK, FFD, D, D, 1, 1);
    // 9. FC2 + residual2 (fp32 out)
    gemm_h<<<dim3(D / 128, TOK / 256), 256, GEMM_SMEM>>>(ff, wfc2, fc2_b, h2, out,
                                                         TOK, D, FFD, FFD, 0, 0);
}

// round 16
// speedup vs baseline: 1.3369x; 1.3352x over previous
#include <cuda_runtime.h>
#include <cuda_fp16.h>
#include <math.h>
#include <stdint.h>

// Problem dims
#define NB   8
#define SEQ  1024
#define TOK  (NB * SEQ)       // 8192
#define D    1152
#define FFD  4608
#define NH   16
#define HD   72
#define QKVN 3456             // 3*D

// ---------------------------------------------------------------------------
// Scratch (device globals)
// ---------------------------------------------------------------------------
__device__ __half g_xln[(size_t)TOK * D];
__device__ __half g_qkv[(size_t)TOK * QKVN];
__device__ __half g_ao[(size_t)TOK * D];
__device__ float  g_h2[(size_t)TOK * D];
__device__ __half g_ff[(size_t)TOK * FFD];
__device__ __half g_wqkv[(size_t)D * QKVN];
__device__ float  g_bqkv[QKVN];
__device__ __half g_wo[(size_t)D * D];
__device__ __half g_wfc1[(size_t)D * FFD];
__device__ __half g_wfc2[(size_t)FFD * D];

// ---------------------------------------------------------------------------
// helpers
// ---------------------------------------------------------------------------
__device__ __forceinline__ uint32_t smem_u32(const void* p) {
    return (uint32_t)__cvta_generic_to_shared(p);
}
__device__ __forceinline__ void ldsm_x4(uint32_t* r, uint32_t addr) {
    asm volatile("ldmatrix.sync.aligned.m8n8.x4.shared.b16 {%0,%1,%2,%3}, [%4];"
                 : "=r"(r[0]), "=r"(r[1]), "=r"(r[2]), "=r"(r[3]) : "r"(addr));
}
__device__ __forceinline__ void ldsm_x4_t(uint32_t* r, uint32_t addr) {
    asm volatile("ldmatrix.sync.aligned.m8n8.x4.trans.shared.b16 {%0,%1,%2,%3}, [%4];"
                 : "=r"(r[0]), "=r"(r[1]), "=r"(r[2]), "=r"(r[3]) : "r"(addr));
}
__device__ __forceinline__ void mma_f16(float* c, const uint32_t* a,
                                        uint32_t b0, uint32_t b1) {
    asm volatile(
        "mma.sync.aligned.m16n8k16.row.col.f32.f16.f16.f32 "
        "{%0,%1,%2,%3}, {%4,%5,%6,%7}, {%8,%9}, {%0,%1,%2,%3};\n"
        : "+f"(c[0]), "+f"(c[1]), "+f"(c[2]), "+f"(c[3])
        : "r"(a[0]), "r"(a[1]), "r"(a[2]), "r"(a[3]), "r"(b0), "r"(b1));
}
__device__ __forceinline__ uint2 f4_to_h4(float4 v) {
    __half2 lo = __floats2half2_rn(v.x, v.y);
    __half2 hi = __floats2half2_rn(v.z, v.w);
    uint2 r;
    r.x = *(uint32_t*)&lo;
    r.y = *(uint32_t*)&hi;
    return r;
}
__device__ __forceinline__ uint32_t packh2(float x, float y) {
    __half2 h = __floats2half2_rn(x, y);
    return *(uint32_t*)&h;
}
__device__ __forceinline__ void cp16(uint32_t dst, const void* src) {
    asm volatile("cp.async.cg.shared.global [%0], [%1], 16;" :: "r"(dst), "l"(src));
}
__device__ __forceinline__ void cp_commit() {
    asm volatile("cp.async.commit_group;");
}

// ---------------------------------------------------------------------------
// Weight conversion / packing
// ---------------------------------------------------------------------------
__global__ void pack_qkv(const float* __restrict__ qw, const float* __restrict__ kw,
                         const float* __restrict__ vw, const float* __restrict__ qb,
                         const float* __restrict__ kb, const float* __restrict__ vb,
                         __half* __restrict__ w16, float* __restrict__ b) {
    int idx = blockIdx.x * blockDim.x + threadIdx.x;
    int e = idx * 4;
    if (e < D * D) {
        int k = e / D, n = e % D;
        size_t o = (size_t)k * QKVN + n;
        *(uint2*)&w16[o]        = f4_to_h4(*(const float4*)(qw + e));
        *(uint2*)&w16[o + 1152] = f4_to_h4(*(const float4*)(kw + e));
        *(uint2*)&w16[o + 2304] = f4_to_h4(*(const float4*)(vw + e));
    }
    if (idx < D) {
        b[idx]        = qb[idx];
        b[idx + 1152] = kb[idx];
        b[idx + 2304] = vb[idx];
    }
}
__global__ void conv_h(const float* __restrict__ src, __half* __restrict__ dst, int n4) {
    int i = blockIdx.x * blockDim.x + threadIdx.x;
    if (i < n4)
        *(uint2*)&dst[(size_t)i * 4] = f4_to_h4(*(const float4*)(src + (size_t)i * 4));
}

// ---------------------------------------------------------------------------
// LayerNorm: fp32 in, fp16 out
// ---------------------------------------------------------------------------
__global__ void ln_kernel(const float* __restrict__ X, const float* __restrict__ gamma,
                          const float* __restrict__ beta, __half* __restrict__ Y) {
    int row = blockIdx.x;
    int tid = threadIdx.x;
    float4 v = ((const float4*)(X + (size_t)row * D))[tid];
    float s  = v.x + v.y + v.z + v.w;
    float sq = v.x * v.x + v.y * v.y + v.z * v.z + v.w * v.w;
    #pragma unroll
    for (int o = 16; o > 0; o >>= 1) {
        s  += __shfl_down_sync(0xffffffffu, s,  o);
        sq += __shfl_down_sync(0xffffffffu, sq, o);
    }
    __shared__ float ss[9], ssq[9];
    int w = tid >> 5, l = tid & 31;
    if (l == 0) { ss[w] = s; ssq[w] = sq; }
    __syncthreads();
    float ts = 0.f, tsq = 0.f;
    #pragma unroll
    for (int i = 0; i < 9; i++) { ts += ss[i]; tsq += ssq[i]; }
    const float invD = 1.0f / (float)D;
    float mean = ts * invD;
    float var  = tsq * invD - mean * mean;
    float rinv = rsqrtf(var + 1e-5f);
    float4 g = ((const float4*)gamma)[tid];
    float4 b = ((const float4*)beta)[tid];
    float4 o;
    o.x = (v.x - mean) * rinv * g.x + b.x;
    o.y = (v.y - mean) * rinv * g.y + b.y;
    o.z = (v.z - mean) * rinv * g.z + b.z;
    o.w = (v.w - mean) * rinv * g.w + b.w;
    *(uint2*)(Y + (size_t)row * D + tid * 4) = f4_to_h4(o);
}

// ---------------------------------------------------------------------------
// fp16 GEMM, 5-stage cp.async pipeline (ring counters).
// CTA tile 128x128x32, 8 warps (2x4), warp tile 64x32 — R12 shape, 2 CTAs/SM.
// Smem: 5 * (128*40 + 32*136) halves = 94,720 B.
// ---------------------------------------------------------------------------
#define GSTG 5
#define AP_  40
#define BP_  136
#define A_ST (128 * AP_)
#define B_ST (32 * BP_)
#define GEMM_SMEM ((GSTG * (A_ST + B_ST)) * 2)

__global__ __launch_bounds__(256, 2)
void gemm_h(const __half* __restrict__ A, const __half* __restrict__ W,
            const float* __restrict__ bias, const float* __restrict__ res,
            void* __restrict__ Cv, int M, int N, int K, int lda,
            int gelu_act, int out_half)
{
    extern __shared__ __half dsm[];
    __half* Asm = dsm;
    __half* Bsm = dsm + GSTG * A_ST;

    int tid  = threadIdx.x;
    int lane = tid & 31;
    int warp = tid >> 5;
    int mwbase = (warp & 1) * 64;
    int nwbase = (warp >> 1) * 32;
    int brow = blockIdx.y * 128;
    int bcol = blockIdx.x * 128;
    int g4 = lane >> 2;
    int t4 = lane & 3;

    int a_row = tid >> 1;
    int a_c   = (tid & 1) * 16;
    int b_row = tid >> 3;
    int b_c   = (tid & 7) * 16;

    const __half* Ap = A + (size_t)(brow + a_row) * lda + a_c;
    const __half* Wp = W + (size_t)b_row * N + bcol + b_c;

    uint32_t as_base = smem_u32(Asm) + (a_row * AP_ + a_c) * 2;
    uint32_t bs_base = smem_u32(Bsm) + (b_row * BP_ + b_c) * 2;

    float acc[4][4][4];
    #pragma unroll
    for (int mt = 0; mt < 4; mt++)
        #pragma unroll
        for (int nt = 0; nt < 4; nt++)
            #pragma unroll
            for (int r = 0; r < 4; r++) acc[mt][nt][r] = 0.f;

    int nk = K / 32;
    // prologue: prefetch stages 0..GSTG-2
    #pragma unroll
    for (int s = 0; s < GSTG - 1; s++) {
        const __half* ap = Ap + s * 32;
        const __half* wp = Wp + (size_t)s * 32 * N;
        uint32_t ad = as_base + s * A_ST * 2;
        uint32_t bd = bs_base + s * B_ST * 2;
        cp16(ad,      ap);
        cp16(ad + 16, ap + 8);
        cp16(bd,      wp);
        cp16(bd + 16, wp + 8);
        cp_commit();
    }

    int cur = 0;            // compute stage
    int pf  = GSTG - 1;     // prefetch target stage
    for (int kt = 0; kt < nk; kt++) {
        asm volatile("cp.async.wait_group %0;" :: "n"(GSTG - 2));
        __syncthreads();
        if (kt + GSTG - 1 < nk) {
            const __half* ap = Ap + (kt + GSTG - 1) * 32;
            const __half* wp = Wp + (size_t)(kt + GSTG - 1) * 32 * N;
            uint32_t ad = as_base + pf * A_ST * 2;
            uint32_t bd = bs_base + pf * B_ST * 2;
            cp16(ad,      ap);
            cp16(ad + 16, ap + 8);
            cp16(bd,      wp);
            cp16(bd + 16, wp + 8);
        }
        cp_commit();
        const __half* Abuf = Asm + cur * A_ST;
        const __half* Bbuf = Bsm + cur * B_ST;
        #pragma unroll
        for (int kk = 0; kk < 32; kk += 16) {
            uint32_t bfr[4][2];
            #pragma unroll
            for (int np = 0; np < 2; np++) {
                int kr = kk + (lane & 7) + ((lane >> 3) & 1) * 8;
                int nc = nwbase + np * 16 + (lane >> 4) * 8;
                uint32_t r[4];
                ldsm_x4_t(r, smem_u32(Bbuf + kr * BP_ + nc));
                bfr[np * 2][0] = r[0]; bfr[np * 2][1] = r[1];
                bfr[np * 2 + 1][0] = r[2]; bfr[np * 2 + 1][1] = r[3];
            }
            #pragma unroll
            for (int mt = 0; mt < 4; mt++) {
                int ar = mwbase + mt * 16 + (lane & 15);
                int ac = kk + (lane >> 4) * 8;
                uint32_t a[4];
                ldsm_x4(a, smem_u32(Abuf + ar * AP_ + ac));
                #pragma unroll
                for (int nt = 0; nt < 4; nt++)
                    mma_f16(acc[mt][nt], a, bfr[nt][0], bfr[nt][1]);
            }
        }
        if (++cur == GSTG) cur = 0;
        if (++pf  == GSTG) pf  = 0;
    }

    __syncthreads();
    #pragma unroll
    for (int mt = 0; mt < 4; mt++) {
        #pragma unroll
        for (int nt = 0; nt < 4; nt++) {
            int col  = bcol + nwbase + nt * 8 + t4 * 2;
            float bx = bias[col], by = bias[col + 1];
            #pragma unroll
            for (int half = 0; half < 2; half++) {
                size_t row = (size_t)(brow + mwbase + mt * 16 + g4 + half * 8);
                float ox = acc[mt][nt][half * 2 + 0] + bx;
                float oy = acc[mt][nt][half * 2 + 1] + by;
                if (gelu_act) {
                    ox = 0.5f * ox * (1.0f + erff(ox * 0.70710678118f));
                    oy = 0.5f * oy * (1.0f + erff(oy * 0.70710678118f));
                }
                if (out_half) {
                    __half* Ch = (__half*)Cv;
                    *(__half2*)(Ch + row * N + col) = __floats2half2_rn(ox, oy);
                } else {
                    if (res) {
                        const float2 r = *(const float2*)(res + row * N + col);
                        ox += r.x; oy += r.y;
                    }
                    *(float2*)((float*)Cv + row * N + col) = make_float2(ox, oy);
                }
            }
        }
    }
}

// ---------------------------------------------------------------------------
// Flash attention with cp.async double-buffered K/V blocks (R12, unchanged)
// ---------------------------------------------------------------------------
#define FAP 88
#define FTS (128 * FAP)

__global__ __launch_bounds__(256, 1)
void flash_attn(const __half* __restrict__ QKV, __half* __restrict__ O) {
    extern __shared__ __half fsm[];
    __half (*Qs)[FAP] = (__half (*)[FAP])fsm;
    __half* Kbuf[2] = { fsm + FTS,     fsm + 2 * FTS };
    __half* Vbuf[2] = { fsm + 3 * FTS, fsm + 4 * FTS };

    int bh = blockIdx.y;
    int b = bh >> 4, h = bh & 15;
    int row0 = blockIdx.x * 128;
    const __half* qbase = QKV + (size_t)b * SEQ * QKVN + h * HD;
    const __half* kbase = qbase + 1152;
    const __half* vbase = qbase + 2304;
    int tid = threadIdx.x;
    int lane = tid & 31;
    int warp = tid >> 5;
    int g4 = lane >> 2;
    int t4 = lane & 3;

    {
        const __half2 sc2 = __float2half2_rn(0.117851130198f);
        for (int i = tid; i < 128 * 18; i += 256) {
            int r = i / 18, c = (i % 18) * 4;
            uint2 u = *(const uint2*)(qbase + (size_t)(row0 + r) * QKVN + c);
            __half2 lo = __hmul2(*(__half2*)&u.x, sc2);
            __half2 hi = __hmul2(*(__half2*)&u.y, sc2);
            uint2 o;
            o.x = *(uint32_t*)&lo;
            o.y = *(uint32_t*)&hi;
            *(uint2*)&Qs[r][c] = o;
        }
        for (int i = tid; i < 128 * 2; i += 256) {
            int r = i >> 1, c = 72 + (i & 1) * 4;
            uint2 z = make_uint2(0u, 0u);
            *(uint2*)&Qs[r][c] = z;
            *(uint2*)&Kbuf[0][r * FAP + c] = z;
            *(uint2*)&Kbuf[1][r * FAP + c] = z;
        }
    }

    for (int i = tid; i < 128 * 9; i += 256) {
        int r = i / 9, c16 = i % 9;
        uint32_t doff = (r * FAP + c16 * 8) * 2;
        cp16(smem_u32(Kbuf[0]) + doff, kbase + (size_t)r * QKVN + c16 * 8);
        cp16(smem_u32(Vbuf[0]) + doff, vbase + (size_t)r * QKVN + c16 * 8);
    }
    cp_commit();
    asm volatile("cp.async.wait_group 0;");
    __syncthreads();

    uint32_t qf[5][4];
    #pragma unroll
    for (int kc = 0; kc < 5; kc++) {
        int ar = warp * 16 + (lane & 15);
        int ac = kc * 16 + (lane >> 4) * 8;
        ldsm_x4(qf[kc], smem_u32(&Qs[ar][ac]));
    }

    float m0 = -1e30f, m1 = -1e30f, l0 = 0.f, l1 = 0.f;
    float o[10][4];
    #pragma unroll
    for (int nt = 0; nt < 10; nt++)
        #pragma unroll
        for (int r = 0; r < 4; r++) o[nt][r] = 0.f;

    for (int jb = 0; jb < 8; jb++) {
        int buf = jb & 1;
        const __half* Ks = Kbuf[buf];
        const __half* Vs = Vbuf[buf];
        if (jb + 1 < 8) {
            int nb = buf ^ 1;
            int j0 = (jb + 1) * 128;
            for (int i = tid; i < 128 * 9; i += 256) {
                int r = i / 9, c16 = i % 9;
                uint32_t doff = (r * FAP + c16 * 8) * 2;
                cp16(smem_u32(Kbuf[nb]) + doff, kbase + (size_t)(j0 + r) * QKVN + c16 * 8);
                cp16(smem_u32(Vbuf[nb]) + doff, vbase + (size_t)(j0 + r) * QKVN + c16 * 8);
            }
            cp_commit();
        }

        float s[16][4];
        #pragma unroll
        for (int nt = 0; nt < 16; nt++)
            #pragma unroll
            for (int r = 0; r < 4; r++) s[nt][r] = 0.f;
        #pragma unroll
        for (int np = 0; np < 8; np++) {
            int nr = np * 16 + (lane & 7) + (lane >> 4) * 8;
            #pragma unroll
            for (int kc = 0; kc < 5; kc++) {
                int nc = kc * 16 + ((lane >> 3) & 1) * 8;
                uint32_t r[4];
                ldsm_x4(r, smem_u32(Ks + nr * FAP + nc));
                mma_f16(s[np * 2],     qf[kc], r[0], r[1]);
                mma_f16(s[np * 2 + 1], qf[kc], r[2], r[3]);
            }
        }

        float cm0 = -1e30f, cm1 = -1e30f;
        #pragma unroll
        for (int nt = 0; nt < 16; nt++) {
            cm0 = fmaxf(cm0, fmaxf(s[nt][0], s[nt][1]));
            cm1 = fmaxf(cm1, fmaxf(s[nt][2], s[nt][3]));
        }
        cm0 = fmaxf(cm0, __shfl_xor_sync(0xffffffffu, cm0, 1));
        cm0 = fmaxf(cm0, __shfl_xor_sync(0xffffffffu, cm0, 2));
        cm1 = fmaxf(cm1, __shfl_xor_sync(0xffffffffu, cm1, 1));
        cm1 = fmaxf(cm1, __shfl_xor_sync(0xffffffffu, cm1, 2));
        float nm0 = fmaxf(m0, cm0);
        float nm1 = fmaxf(m1, cm1);
        float f0 = __expf(m0 - nm0);
        float f1 = __expf(m1 - nm1);
        m0 = nm0; m1 = nm1;
        float sum0 = 0.f, sum1 = 0.f;
        #pragma unroll
        for (int nt = 0; nt < 16; nt++) {
            s[nt][0] = __expf(s[nt][0] - nm0);
            s[nt][1] = __expf(s[nt][1] - nm0);
            s[nt][2] = __expf(s[nt][2] - nm1);
            s[nt][3] = __expf(s[nt][3] - nm1);
            sum0 += s[nt][0] + s[nt][1];
            sum1 += s[nt][2] + s[nt][3];
        }
        l0 = l0 * f0 + sum0;
        l1 = l1 * f1 + sum1;
        #pragma unroll
        for (int nt = 0; nt < 10; nt++) {
            o[nt][0] *= f0; o[nt][1] *= f0;
            o[nt][2] *= f1; o[nt][3] *= f1;
        }

        #pragma unroll
        for (int kc2 = 0; kc2 < 8; kc2++) {
            uint32_t a[4];
            a[0] = packh2(s[kc2 * 2][0],     s[kc2 * 2][1]);
            a[1] = packh2(s[kc2 * 2][2],     s[kc2 * 2][3]);
            a[2] = packh2(s[kc2 * 2 + 1][0], s[kc2 * 2 + 1][1]);
            a[3] = packh2(s[kc2 * 2 + 1][2], s[kc2 * 2 + 1][3]);
            int kr = kc2 * 16 + (lane & 7) + ((lane >> 3) & 1) * 8;
            #pragma unroll
            for (int np = 0; np < 5; np++) {
                int nc = np * 16 + (lane >> 4) * 8;
                uint32_t r[4];
                ldsm_x4_t(r, smem_u32(Vs + kr * FAP + nc));
                mma_f16(o[np * 2],     a, r[0], r[1]);
                mma_f16(o[np * 2 + 1], a, r[2], r[3]);
            }
        }
        if (jb + 1 < 8) {
            asm volatile("cp.async.wait_group 0;");
            __syncthreads();
        }
    }

    l0 += __shfl_xor_sync(0xffffffffu, l0, 1);
    l0 += __shfl_xor_sync(0xffffffffu, l0, 2);
    l1 += __shfl_xor_sync(0xffffffffu, l1, 1);
    l1 += __shfl_xor_sync(0xffffffffu, l1, 2);
    float inv0 = 1.0f / l0;
    float inv1 = 1.0f / l1;
    #pragma unroll
    for (int nt = 0; nt < 9; nt++) {
        int col = h * HD + nt * 8 + t4 * 2;
        size_t r = (size_t)b * SEQ + row0 + warp * 16 + g4;
        *(__half2*)(O + r * D + col)       = __floats2half2_rn(o[nt][0] * inv0, o[nt][1] * inv0);
        *(__half2*)(O + (r + 8) * D + col) = __floats2half2_rn(o[nt][2] * inv1, o[nt][3] * inv1);
    }
}

// ---------------------------------------------------------------------------
// Launch
// ---------------------------------------------------------------------------
extern "C" void kernel_launch(void* const* d_in, const int* in_sizes, int n_in,
                              void* d_out, int out_size) {
    const float* hs    = (const float*)d_in[0];
    const float* ln1_w = (const float*)d_in[1];
    const float* ln1_b = (const float*)d_in[2];
    const float* q_w   = (const float*)d_in[3];
    const float* q_b   = (const float*)d_in[4];
    const float* k_w   = (const float*)d_in[5];
    const float* k_b   = (const float*)d_in[6];
    const float* v_w   = (const float*)d_in[7];
    const float* v_b   = (const float*)d_in[8];
    const float* o_w   = (const float*)d_in[9];
    const float* o_b   = (const float*)d_in[10];
    const float* ln2_w = (const float*)d_in[11];
    const float* ln2_b = (const float*)d_in[12];
    const float* fc1_w = (const float*)d_in[13];
    const float* fc1_b = (const float*)d_in[14];
    const float* fc2_w = (const float*)d_in[15];
    const float* fc2_b = (const float*)d_in[16];
    float* out = (float*)d_out;

    __half *xln, *qkv, *ao, *ff, *wqkv, *wo, *wfc1, *wfc2;
    float *h2, *bqkv;
    cudaGetSymbolAddress((void**)&xln,  g_xln);
    cudaGetSymbolAddress((void**)&qkv,  g_qkv);
    cudaGetSymbolAddress((void**)&ao,   g_ao);
    cudaGetSymbolAddress((void**)&h2,   g_h2);
    cudaGetSymbolAddress((void**)&ff,   g_ff);
    cudaGetSymbolAddress((void**)&wqkv, g_wqkv);
    cudaGetSymbolAddress((void**)&bqkv, g_bqkv);
    cudaGetSymbolAddress((void**)&wo,   g_wo);
    cudaGetSymbolAddress((void**)&wfc1, g_wfc1);
    cudaGetSymbolAddress((void**)&wfc2, g_wfc2);

    const int FA_SMEM = 5 * FTS * (int)sizeof(__half);          // 112,640 B
    cudaFuncSetAttribute(flash_attn, cudaFuncAttributeMaxDynamicSharedMemorySize,
                         FA_SMEM);
    cudaFuncSetAttribute(gemm_h, cudaFuncAttributeMaxDynamicSharedMemorySize,
                         GEMM_SMEM);                            // 94,720 B

    // 0. weight conversion / packing
    pack_qkv<<<(D * D / 4 + 255) / 256, 256>>>(q_w, k_w, v_w, q_b, k_b, v_b, wqkv, bqkv);
    conv_h<<<(D * D / 4 + 255) / 256, 256>>>(o_w, wo, D * D / 4);
    conv_h<<<(D * FFD / 4 + 255) / 256, 256>>>(fc1_w, wfc1, D * FFD / 4);
    conv_h<<<(FFD * D / 4 + 255) / 256, 256>>>(fc2_w, wfc2, FFD * D / 4);

    // 1. LN1 -> fp16
    ln_kernel<<<TOK, 288>>>(hs, ln1_w, ln1_b, xln);
    // 2. fused QKV projection
    gemm_h<<<dim3(QKVN / 128, TOK / 128), 256, GEMM_SMEM>>>(xln, wqkv, bqkv, nullptr, qkv,
                                                            TOK, QKVN, D, D, 0, 1);
    // 3-5. fused attention
    flash_attn<<<dim3(SEQ / 128, NB * NH), 256, FA_SMEM>>>(qkv, ao);
    // 6. O projection + residual1 (fp32 out)
    gemm_h<<<dim3(D / 128, TOK / 128), 256, GEMM_SMEM>>>(ao, wo, o_b, hs, h2,
                                                         TOK, D, D, D, 0, 0);
    // 7. LN2 -> fp16
    ln_kernel<<<TOK, 288>>>(h2, ln2_w, ln2_b, xln);
    // 8. FC1 + GELU (fp16 out)
    gemm_h<<<dim3(FFD / 128, TOK / 128), 256, GEMM_SMEM>>>(xln, wfc1, fc1_b, nullptr, ff,
                                                           TOK, FFD, D, D, 1, 1);
    // 9. FC2 + residual2 (fp32 out)
    gemm_h<<<dim3(D / 128, TOK / 128), 256, GEMM_SMEM>>>(ff, wfc2, fc2_b, h2, out,
                                                         TOK, D, FFD, FFD, 0, 0);
}

// round 17
// speedup vs baseline: 1.3369x; 1.0000x over previous
#include <cuda_runtime.h>
#include <cuda_fp16.h>
#include <math.h>
#include <stdint.h>

// Problem dims
#define NB   8
#define SEQ  1024
#define TOK  (NB * SEQ)       // 8192
#define D    1152
#define FFD  4608
#define NH   16
#define HD   72
#define QKVN 3456             // 3*D

// ---------------------------------------------------------------------------
// Scratch (device globals)
// ---------------------------------------------------------------------------
__device__ __half g_xln[(size_t)TOK * D];
__device__ __half g_qkv[(size_t)TOK * QKVN];
__device__ __half g_ao[(size_t)TOK * D];
__device__ float  g_h2[(size_t)TOK * D];
__device__ __half g_ff[(size_t)TOK * FFD];
__device__ __half g_wqkv[(size_t)D * QKVN];
__device__ float  g_bqkv[QKVN];
__device__ __half g_wo[(size_t)D * D];
__device__ __half g_wfc1[(size_t)D * FFD];
__device__ __half g_wfc2[(size_t)FFD * D];

// ---------------------------------------------------------------------------
// helpers
// ---------------------------------------------------------------------------
__device__ __forceinline__ uint32_t smem_u32(const void* p) {
    return (uint32_t)__cvta_generic_to_shared(p);
}
__device__ __forceinline__ void ldsm_x4(uint32_t* r, uint32_t addr) {
    asm volatile("ldmatrix.sync.aligned.m8n8.x4.shared.b16 {%0,%1,%2,%3}, [%4];"
                 : "=r"(r[0]), "=r"(r[1]), "=r"(r[2]), "=r"(r[3]) : "r"(addr));
}
__device__ __forceinline__ void ldsm_x4_t(uint32_t* r, uint32_t addr) {
    asm volatile("ldmatrix.sync.aligned.m8n8.x4.trans.shared.b16 {%0,%1,%2,%3}, [%4];"
                 : "=r"(r[0]), "=r"(r[1]), "=r"(r[2]), "=r"(r[3]) : "r"(addr));
}
__device__ __forceinline__ void mma_f16(float* c, const uint32_t* a,
                                        uint32_t b0, uint32_t b1) {
    asm volatile(
        "mma.sync.aligned.m16n8k16.row.col.f32.f16.f16.f32 "
        "{%0,%1,%2,%3}, {%4,%5,%6,%7}, {%8,%9}, {%0,%1,%2,%3};\n"
        : "+f"(c[0]), "+f"(c[1]), "+f"(c[2]), "+f"(c[3])
        : "r"(a[0]), "r"(a[1]), "r"(a[2]), "r"(a[3]), "r"(b0), "r"(b1));
}
__device__ __forceinline__ uint2 f4_to_h4(float4 v) {
    __half2 lo = __floats2half2_rn(v.x, v.y);
    __half2 hi = __floats2half2_rn(v.z, v.w);
    uint2 r;
    r.x = *(uint32_t*)&lo;
    r.y = *(uint32_t*)&hi;
    return r;
}
__device__ __forceinline__ uint32_t packh2(float x, float y) {
    __half2 h = __floats2half2_rn(x, y);
    return *(uint32_t*)&h;
}
__device__ __forceinline__ void cp16(uint32_t dst, const void* src) {
    asm volatile("cp.async.cg.shared.global [%0], [%1], 16;" :: "r"(dst), "l"(src));
}
__device__ __forceinline__ void cp_commit() {
    asm volatile("cp.async.commit_group;");
}

// ---------------------------------------------------------------------------
// Weight conversion / packing
// ---------------------------------------------------------------------------
__global__ void pack_qkv(const float* __restrict__ qw, const float* __restrict__ kw,
                         const float* __restrict__ vw, const float* __restrict__ qb,
                         const float* __restrict__ kb, const float* __restrict__ vb,
                         __half* __restrict__ w16, float* __restrict__ b) {
    int idx = blockIdx.x * blockDim.x + threadIdx.x;
    int e = idx * 4;
    if (e < D * D) {
        int k = e / D, n = e % D;
        size_t o = (size_t)k * QKVN + n;
        *(uint2*)&w16[o]        = f4_to_h4(*(const float4*)(qw + e));
        *(uint2*)&w16[o + 1152] = f4_to_h4(*(const float4*)(kw + e));
        *(uint2*)&w16[o + 2304] = f4_to_h4(*(const float4*)(vw + e));
    }
    if (idx < D) {
        b[idx]        = qb[idx];
        b[idx + 1152] = kb[idx];
        b[idx + 2304] = vb[idx];
    }
}
__global__ void conv_h(const float* __restrict__ src, __half* __restrict__ dst, int n4) {
    int i = blockIdx.x * blockDim.x + threadIdx.x;
    if (i < n4)
        *(uint2*)&dst[(size_t)i * 4] = f4_to_h4(*(const float4*)(src + (size_t)i * 4));
}

// ---------------------------------------------------------------------------
// LayerNorm: fp32 in, fp16 out
// ---------------------------------------------------------------------------
__global__ void ln_kernel(const float* __restrict__ X, const float* __restrict__ gamma,
                          const float* __restrict__ beta, __half* __restrict__ Y) {
    int row = blockIdx.x;
    int tid = threadIdx.x;
    float4 v = ((const float4*)(X + (size_t)row * D))[tid];
    float s  = v.x + v.y + v.z + v.w;
    float sq = v.x * v.x + v.y * v.y + v.z * v.z + v.w * v.w;
    #pragma unroll
    for (int o = 16; o > 0; o >>= 1) {
        s  += __shfl_down_sync(0xffffffffu, s,  o);
        sq += __shfl_down_sync(0xffffffffu, sq, o);
    }
    __shared__ float ss[9], ssq[9];
    int w = tid >> 5, l = tid & 31;
    if (l == 0) { ss[w] = s; ssq[w] = sq; }
    __syncthreads();
    float ts = 0.f, tsq = 0.f;
    #pragma unroll
    for (int i = 0; i < 9; i++) { ts += ss[i]; tsq += ssq[i]; }
    const float invD = 1.0f / (float)D;
    float mean = ts * invD;
    float var  = tsq * invD - mean * mean;
    float rinv = rsqrtf(var + 1e-5f);
    float4 g = ((const float4*)gamma)[tid];
    float4 b = ((const float4*)beta)[tid];
    float4 o;
    o.x = (v.x - mean) * rinv * g.x + b.x;
    o.y = (v.y - mean) * rinv * g.y + b.y;
    o.z = (v.z - mean) * rinv * g.z + b.z;
    o.w = (v.w - mean) * rinv * g.w + b.w;
    *(uint2*)(Y + (size_t)row * D + tid * 4) = f4_to_h4(o);
}

// ---------------------------------------------------------------------------
// fp16 GEMM, 5-stage cp.async pipeline (ring counters).
// CTA tile 128x128x32, 8 warps (2x4), warp tile 64x32 — R12 shape, 2 CTAs/SM.
// Smem: 5 * (128*40 + 32*136) halves = 94,720 B.
// ---------------------------------------------------------------------------
#define GSTG 5
#define AP_  40
#define BP_  136
#define A_ST (128 * AP_)
#define B_ST (32 * BP_)
#define GEMM_SMEM ((GSTG * (A_ST + B_ST)) * 2)

__global__ __launch_bounds__(256, 2)
void gemm_h(const __half* __restrict__ A, const __half* __restrict__ W,
            const float* __restrict__ bias, const float* __restrict__ res,
            void* __restrict__ Cv, int M, int N, int K, int lda,
            int gelu_act, int out_half)
{
    extern __shared__ __half dsm[];
    __half* Asm = dsm;
    __half* Bsm = dsm + GSTG * A_ST;

    int tid  = threadIdx.x;
    int lane = tid & 31;
    int warp = tid >> 5;
    int mwbase = (warp & 1) * 64;
    int nwbase = (warp >> 1) * 32;
    int brow = blockIdx.y * 128;
    int bcol = blockIdx.x * 128;
    int g4 = lane >> 2;
    int t4 = lane & 3;

    int a_row = tid >> 1;
    int a_c   = (tid & 1) * 16;
    int b_row = tid >> 3;
    int b_c   = (tid & 7) * 16;

    const __half* Ap = A + (size_t)(brow + a_row) * lda + a_c;
    const __half* Wp = W + (size_t)b_row * N + bcol + b_c;

    uint32_t as_base = smem_u32(Asm) + (a_row * AP_ + a_c) * 2;
    uint32_t bs_base = smem_u32(Bsm) + (b_row * BP_ + b_c) * 2;

    float acc[4][4][4];
    #pragma unroll
    for (int mt = 0; mt < 4; mt++)
        #pragma unroll
        for (int nt = 0; nt < 4; nt++)
            #pragma unroll
            for (int r = 0; r < 4; r++) acc[mt][nt][r] = 0.f;

    int nk = K / 32;
    // prologue: prefetch stages 0..GSTG-2
    #pragma unroll
    for (int s = 0; s < GSTG - 1; s++) {
        const __half* ap = Ap + s * 32;
        const __half* wp = Wp + (size_t)s * 32 * N;
        uint32_t ad = as_base + s * A_ST * 2;
        uint32_t bd = bs_base + s * B_ST * 2;
        cp16(ad,      ap);
        cp16(ad + 16, ap + 8);
        cp16(bd,      wp);
        cp16(bd + 16, wp + 8);
        cp_commit();
    }

    int cur = 0;            // compute stage
    int pf  = GSTG - 1;     // prefetch target stage
    for (int kt = 0; kt < nk; kt++) {
        asm volatile("cp.async.wait_group %0;" :: "n"(GSTG - 2));
        __syncthreads();
        if (kt + GSTG - 1 < nk) {
            const __half* ap = Ap + (kt + GSTG - 1) * 32;
            const __half* wp = Wp + (size_t)(kt + GSTG - 1) * 32 * N;
            uint32_t ad = as_base + pf * A_ST * 2;
            uint32_t bd = bs_base + pf * B_ST * 2;
            cp16(ad,      ap);
            cp16(ad + 16, ap + 8);
            cp16(bd,      wp);
            cp16(bd + 16, wp + 8);
        }
        cp_commit();
        const __half* Abuf = Asm + cur * A_ST;
        const __half* Bbuf = Bsm + cur * B_ST;
        #pragma unroll
        for (int kk = 0; kk < 32; kk += 16) {
            uint32_t bfr[4][2];
            #pragma unroll
            for (int np = 0; np < 2; np++) {
                int kr = kk + (lane & 7) + ((lane >> 3) & 1) * 8;
                int nc = nwbase + np * 16 + (lane >> 4) * 8;
                uint32_t r[4];
                ldsm_x4_t(r, smem_u32(Bbuf + kr * BP_ + nc));
                bfr[np * 2][0] = r[0]; bfr[np * 2][1] = r[1];
                bfr[np * 2 + 1][0] = r[2]; bfr[np * 2 + 1][1] = r[3];
            }
            #pragma unroll
            for (int mt = 0; mt < 4; mt++) {
                int ar = mwbase + mt * 16 + (lane & 15);
                int ac = kk + (lane >> 4) * 8;
                uint32_t a[4];
                ldsm_x4(a, smem_u32(Abuf + ar * AP_ + ac));
                #pragma unroll
                for (int nt = 0; nt < 4; nt++)
                    mma_f16(acc[mt][nt], a, bfr[nt][0], bfr[nt][1]);
            }
        }
        if (++cur == GSTG) cur = 0;
        if (++pf  == GSTG) pf  = 0;
    }

    __syncthreads();
    #pragma unroll
    for (int mt = 0; mt < 4; mt++) {
        #pragma unroll
        for (int nt = 0; nt < 4; nt++) {
            int col  = bcol + nwbase + nt * 8 + t4 * 2;
            float bx = bias[col], by = bias[col + 1];
            #pragma unroll
            for (int half = 0; half < 2; half++) {
                size_t row = (size_t)(brow + mwbase + mt * 16 + g4 + half * 8);
                float ox = acc[mt][nt][half * 2 + 0] + bx;
                float oy = acc[mt][nt][half * 2 + 1] + by;
                if (gelu_act) {
                    ox = 0.5f * ox * (1.0f + erff(ox * 0.70710678118f));
                    oy = 0.5f * oy * (1.0f + erff(oy * 0.70710678118f));
                }
                if (out_half) {
                    __half* Ch = (__half*)Cv;
                    *(__half2*)(Ch + row * N + col) = __floats2half2_rn(ox, oy);
                } else {
                    if (res) {
                        const float2 r = *(const float2*)(res + row * N + col);
                        ox += r.x; oy += r.y;
                    }
                    *(float2*)((float*)Cv + row * N + col) = make_float2(ox, oy);
                }
            }
        }
    }
}

// ---------------------------------------------------------------------------
// Flash attention with cp.async double-buffered K/V blocks (R12, unchanged)
// ---------------------------------------------------------------------------
#define FAP 88
#define FTS (128 * FAP)

__global__ __launch_bounds__(256, 1)
void flash_attn(const __half* __restrict__ QKV, __half* __restrict__ O) {
    extern __shared__ __half fsm[];
    __half (*Qs)[FAP] = (__half (*)[FAP])fsm;
    __half* Kbuf[2] = { fsm + FTS,     fsm + 2 * FTS };
    __half* Vbuf[2] = { fsm + 3 * FTS, fsm + 4 * FTS };

    int bh = blockIdx.y;
    int b = bh >> 4, h = bh & 15;
    int row0 = blockIdx.x * 128;
    const __half* qbase = QKV + (size_t)b * SEQ * QKVN + h * HD;
    const __half* kbase = qbase + 1152;
    const __half* vbase = qbase + 2304;
    int tid = threadIdx.x;
    int lane = tid & 31;
    int warp = tid >> 5;
    int g4 = lane >> 2;
    int t4 = lane & 3;

    {
        const __half2 sc2 = __float2half2_rn(0.117851130198f);
        for (int i = tid; i < 128 * 18; i += 256) {
            int r = i / 18, c = (i % 18) * 4;
            uint2 u = *(const uint2*)(qbase + (size_t)(row0 + r) * QKVN + c);
            __half2 lo = __hmul2(*(__half2*)&u.x, sc2);
            __half2 hi = __hmul2(*(__half2*)&u.y, sc2);
            uint2 o;
            o.x = *(uint32_t*)&lo;
            o.y = *(uint32_t*)&hi;
            *(uint2*)&Qs[r][c] = o;
        }
        for (int i = tid; i < 128 * 2; i += 256) {
            int r = i >> 1, c = 72 + (i & 1) * 4;
            uint2 z = make_uint2(0u, 0u);
            *(uint2*)&Qs[r][c] = z;
            *(uint2*)&Kbuf[0][r * FAP + c] = z;
            *(uint2*)&Kbuf[1][r * FAP + c] = z;
        }
    }

    for (int i = tid; i < 128 * 9; i += 256) {
        int r = i / 9, c16 = i % 9;
        uint32_t doff = (r * FAP + c16 * 8) * 2;
        cp16(smem_u32(Kbuf[0]) + doff, kbase + (size_t)r * QKVN + c16 * 8);
        cp16(smem_u32(Vbuf[0]) + doff, vbase + (size_t)r * QKVN + c16 * 8);
    }
    cp_commit();
    asm volatile("cp.async.wait_group 0;");
    __syncthreads();

    uint32_t qf[5][4];
    #pragma unroll
    for (int kc = 0; kc < 5; kc++) {
        int ar = warp * 16 + (lane & 15);
        int ac = kc * 16 + (lane >> 4) * 8;
        ldsm_x4(qf[kc], smem_u32(&Qs[ar][ac]));
    }

    float m0 = -1e30f, m1 = -1e30f, l0 = 0.f, l1 = 0.f;
    float o[10][4];
    #pragma unroll
    for (int nt = 0; nt < 10; nt++)
        #pragma unroll
        for (int r = 0; r < 4; r++) o[nt][r] = 0.f;

    for (int jb = 0; jb < 8; jb++) {
        int buf = jb & 1;
        const __half* Ks = Kbuf[buf];
        const __half* Vs = Vbuf[buf];
        if (jb + 1 < 8) {
            int nb = buf ^ 1;
            int j0 = (jb + 1) * 128;
            for (int i = tid; i < 128 * 9; i += 256) {
                int r = i / 9, c16 = i % 9;
                uint32_t doff = (r * FAP + c16 * 8) * 2;
                cp16(smem_u32(Kbuf[nb]) + doff, kbase + (size_t)(j0 + r) * QKVN + c16 * 8);
                cp16(smem_u32(Vbuf[nb]) + doff, vbase + (size_t)(j0 + r) * QKVN + c16 * 8);
            }
            cp_commit();
        }

        float s[16][4];
        #pragma unroll
        for (int nt = 0; nt < 16; nt++)
            #pragma unroll
            for (int r = 0; r < 4; r++) s[nt][r] = 0.f;
        #pragma unroll
        for (int np = 0; np < 8; np++) {
            int nr = np * 16 + (lane & 7) + (lane >> 4) * 8;
            #pragma unroll
            for (int kc = 0; kc < 5; kc++) {
                int nc = kc * 16 + ((lane >> 3) & 1) * 8;
                uint32_t r[4];
                ldsm_x4(r, smem_u32(Ks + nr * FAP + nc));
                mma_f16(s[np * 2],     qf[kc], r[0], r[1]);
                mma_f16(s[np * 2 + 1], qf[kc], r[2], r[3]);
            }
        }

        float cm0 = -1e30f, cm1 = -1e30f;
        #pragma unroll
        for (int nt = 0; nt < 16; nt++) {
            cm0 = fmaxf(cm0, fmaxf(s[nt][0], s[nt][1]));
            cm1 = fmaxf(cm1, fmaxf(s[nt][2], s[nt][3]));
        }
        cm0 = fmaxf(cm0, __shfl_xor_sync(0xffffffffu, cm0, 1));
        cm0 = fmaxf(cm0, __shfl_xor_sync(0xffffffffu, cm0, 2));
        cm1 = fmaxf(cm1, __shfl_xor_sync(0xffffffffu, cm1, 1));
        cm1 = fmaxf(cm1, __shfl_xor_sync(0xffffffffu, cm1, 2));
        float nm0 = fmaxf(m0, cm0);
        float nm1 = fmaxf(m1, cm1);
        float f0 = __expf(m0 - nm0);
        float f1 = __expf(m1 - nm1);
        m0 = nm0; m1 = nm1;
        float sum0 = 0.f, sum1 = 0.f;
        #pragma unroll
        for (int nt = 0; nt < 16; nt++) {
            s[nt][0] = __expf(s[nt][0] - nm0);
            s[nt][1] = __expf(s[nt][1] - nm0);
            s[nt][2] = __expf(s[nt][2] - nm1);
            s[nt][3] = __expf(s[nt][3] - nm1);
            sum0 += s[nt][0] + s[nt][1];
            sum1 += s[nt][2] + s[nt][3];
        }
        l0 = l0 * f0 + sum0;
        l1 = l1 * f1 + sum1;
        #pragma unroll
        for (int nt = 0; nt < 10; nt++) {
            o[nt][0] *= f0; o[nt][1] *= f0;
            o[nt][2] *= f1; o[nt][3] *= f1;
        }

        #pragma unroll
        for (int kc2 = 0; kc2 < 8; kc2++) {
            uint32_t a[4];
            a[0] = packh2(s[kc2 * 2][0],     s[kc2 * 2][1]);
            a[1] = packh2(s[kc2 * 2][2],     s[kc2 * 2][3]);
            a[2] = packh2(s[kc2 * 2 + 1][0], s[kc2 * 2 + 1][1]);
            a[3] = packh2(s[kc2 * 2 + 1][2], s[kc2 * 2 + 1][3]);
            int kr = kc2 * 16 + (lane & 7) + ((lane >> 3) & 1) * 8;
            #pragma unroll
            for (int np = 0; np < 5; np++) {
                int nc = np * 16 + (lane >> 4) * 8;
                uint32_t r[4];
                ldsm_x4_t(r, smem_u32(Vs + kr * FAP + nc));
                mma_f16(o[np * 2],     a, r[0], r[1]);
                mma_f16(o[np * 2 + 1], a, r[2], r[3]);
            }
        }
        if (jb + 1 < 8) {
            asm volatile("cp.async.wait_group 0;");
            __syncthreads();
        }
    }

    l0 += __shfl_xor_sync(0xffffffffu, l0, 1);
    l0 += __shfl_xor_sync(0xffffffffu, l0, 2);
    l1 += __shfl_xor_sync(0xffffffffu, l1, 1);
    l1 += __shfl_xor_sync(0xffffffffu, l1, 2);
    float inv0 = 1.0f / l0;
    float inv1 = 1.0f / l1;
    #pragma unroll
    for (int nt = 0; nt < 9; nt++) {
        int col = h * HD + nt * 8 + t4 * 2;
        size_t r = (size_t)b * SEQ + row0 + warp * 16 + g4;
        *(__half2*)(O + r * D + col)       = __floats2half2_rn(o[nt][0] * inv0, o[nt][1] * inv0);
        *(__half2*)(O + (r + 8) * D + col) = __floats2half2_rn(o[nt][2] * inv1, o[nt][3] * inv1);
    }
}

// ---------------------------------------------------------------------------
// Launch
// ---------------------------------------------------------------------------
extern "C" void kernel_launch(void* const* d_in, const int* in_sizes, int n_in,
                              void* d_out, int out_size) {
    const float* hs    = (const float*)d_in[0];
    const float* ln1_w = (const float*)d_in[1];
    const float* ln1_b = (const float*)d_in[2];
    const float* q_w   = (const float*)d_in[3];
    const float* q_b   = (const float*)d_in[4];
    const float* k_w   = (const float*)d_in[5];
    const float* k_b   = (const float*)d_in[6];
    const float* v_w   = (const float*)d_in[7];
    const float* v_b   = (const float*)d_in[8];
    const float* o_w   = (const float*)d_in[9];
    const float* o_b   = (const float*)d_in[10];
    const float* ln2_w = (const float*)d_in[11];
    const float* ln2_b = (const float*)d_in[12];
    const float* fc1_w = (const float*)d_in[13];
    const float* fc1_b = (const float*)d_in[14];
    const float* fc2_w = (const float*)d_in[15];
    const float* fc2_b = (const float*)d_in[16];
    float* out = (float*)d_out;

    __half *xln, *qkv, *ao, *ff, *wqkv, *wo, *wfc1, *wfc2;
    float *h2, *bqkv;
    cudaGetSymbolAddress((void**)&xln,  g_xln);
    cudaGetSymbolAddress((void**)&qkv,  g_qkv);
    cudaGetSymbolAddress((void**)&ao,   g_ao);
    cudaGetSymbolAddress((void**)&h2,   g_h2);
    cudaGetSymbolAddress((void**)&ff,   g_ff);
    cudaGetSymbolAddress((void**)&wqkv, g_wqkv);
    cudaGetSymbolAddress((void**)&bqkv, g_bqkv);
    cudaGetSymbolAddress((void**)&wo,   g_wo);
    cudaGetSymbolAddress((void**)&wfc1, g_wfc1);
    cudaGetSymbolAddress((void**)&wfc2, g_wfc2);

    const int FA_SMEM = 5 * FTS * (int)sizeof(__half);          // 112,640 B
    cudaFuncSetAttribute(flash_attn, cudaFuncAttributeMaxDynamicSharedMemorySize,
                         FA_SMEM);
    cudaFuncSetAttribute(gemm_h, cudaFuncAttributeMaxDynamicSharedMemorySize,
                         GEMM_SMEM);                            // 94,720 B

    // 0. weight conversion / packing
    pack_qkv<<<(D * D / 4 + 255) / 256, 256>>>(q_w, k_w, v_w, q_b, k_b, v_b, wqkv, bqkv);
    conv_h<<<(D * D / 4 + 255) / 256, 256>>>(o_w, wo, D * D / 4);
    conv_h<<<(D * FFD / 4 + 255) / 256, 256>>>(fc1_w, wfc1, D * FFD / 4);
    conv_h<<<(FFD * D / 4 + 255) / 256, 256>>>(fc2_w, wfc2, FFD * D / 4);

    // 1. LN1 -> fp16
    ln_kernel<<<TOK, 288>>>(hs, ln1_w, ln1_b, xln);
    // 2. fused QKV projection
    gemm_h<<<dim3(QKVN / 128, TOK / 128), 256, GEMM_SMEM>>>(xln, wqkv, bqkv, nullptr, qkv,
                                                            TOK, QKVN, D, D, 0, 1);
    // 3-5. fused attention
    flash_attn<<<dim3(SEQ / 128, NB * NH), 256, FA_SMEM>>>(qkv, ao);
    // 6. O projection + residual1 (fp32 out)
    gemm_h<<<dim3(D / 128, TOK / 128), 256, GEMM_SMEM>>>(ao, wo, o_b, hs, h2,
                                                         TOK, D, D, D, 0, 0);
    // 7. LN2 -> fp16
    ln_kernel<<<TOK, 288>>>(h2, ln2_w, ln2_b, xln);
    // 8. FC1 + GELU (fp16 out)
    gemm_h<<<dim3(FFD / 128, TOK / 128), 256, GEMM_SMEM>>>(xln, wfc1, fc1_b, nullptr, ff,
                                                           TOK, FFD, D, D, 1, 1);
    // 9. FC2 + residual2 (fp32 out)
    gemm_h<<<dim3(D / 128, TOK / 128), 256, GEMM_SMEM>>>(ff, wfc2, fc2_b, h2, out,
                                                         TOK, D, FFD, FFD, 0, 0);
}